// round 16
// baseline (speedup 1.0000x reference)
#include <cuda_runtime.h>
#include <cuda_bf16.h>
#include <math_constants.h>
#include <cstdint>

// Problem constants
#define B_   16
#define L_   1024
#define D_   128
#define H_   8
#define HD_  16
#define ROWS (B_ * L_)          // 16384
#define LN_EPS 1e-5f
#define NMASKW (B_ * L_ * L_ / 32)   // 524288

// ---------------- scratch (device globals) ---------------------------------
__device__ float g_q  [ROWS * D_];                 // Q fp32, PRE-SCALED
__device__ __nv_bfloat16 g_kh[ROWS * D_];
__device__ __nv_bfloat16 g_kl[ROWS * D_];
__device__ __nv_bfloat16 g_vh[ROWS * D_];
__device__ __nv_bfloat16 g_xh[ROWS * D_];
__device__ __nv_bfloat16 g_xl[ROWS * D_];
__device__ __nv_bfloat16 g_wqh[D_ * 3 * D_];
__device__ __nv_bfloat16 g_wql[D_ * 3 * D_];
__device__ __nv_bfloat16 g_w1h[D_ * D_];
__device__ __nv_bfloat16 g_w1l[D_ * D_];
__device__ __nv_bfloat16 g_w2h[D_ * D_];
__device__ __nv_bfloat16 g_w2l[D_ * D_];
__device__ __nv_bfloat16 g_x1h[ROWS * D_];
__device__ __nv_bfloat16 g_x1l[ROWS * D_];
__device__ float g_ctx[ROWS * D_];
__device__ uint32_t g_maskbits[NMASKW];
__device__ int g_mask_is_i32;

// ============================ helpers ======================================
__device__ __forceinline__ uint32_t smem_u32(const void* p) {
    uint32_t a;
    asm("{ .reg .u64 t; cvta.to.shared.u64 t, %1; cvt.u32.u64 %0, t; }"
        : "=r"(a) : "l"(p));
    return a;
}
__device__ __forceinline__ uint32_t pack_bf16x2(float e, float o) {
    uint32_t r;
    asm("cvt.rn.bf16x2.f32 %0, %1, %2;" : "=r"(r) : "f"(o), "f"(e));
    return r;
}
__device__ __forceinline__ float ex2f(float x) {
    float y; asm("ex2.approx.f32 %0, %1;" : "=f"(y) : "f"(x)); return y;
}
__device__ __forceinline__ float bfr(float x) {
    return __bfloat162float(__float2bfloat16_rn(x));
}
__device__ __forceinline__ void mma_bf16(float* c, const uint32_t* a, uint32_t b0, uint32_t b1) {
    asm volatile("mma.sync.aligned.m16n8k16.row.col.f32.bf16.bf16.f32 "
        "{%0,%1,%2,%3}, {%4,%5,%6,%7}, {%8,%9}, {%0,%1,%2,%3};"
        : "+f"(c[0]), "+f"(c[1]), "+f"(c[2]), "+f"(c[3])
        : "r"(a[0]), "r"(a[1]), "r"(a[2]), "r"(a[3]), "r"(b0), "r"(b1));
}
__device__ __forceinline__ void ldm_x4(uint32_t* r, uint32_t addr) {
    asm volatile("ldmatrix.sync.aligned.m8n8.x4.shared.b16 {%0,%1,%2,%3}, [%4];"
        : "=r"(r[0]), "=r"(r[1]), "=r"(r[2]), "=r"(r[3]) : "r"(addr));
}
__device__ __forceinline__ void ldm_x4_t(uint32_t* r, uint32_t addr) {
    asm volatile("ldmatrix.sync.aligned.m8n8.x4.trans.shared.b16 {%0,%1,%2,%3}, [%4];"
        : "=r"(r[0]), "=r"(r[1]), "=r"(r[2]), "=r"(r[3]) : "r"(addr));
}
__device__ __forceinline__ void cp16(uint32_t dst, const void* src) {
    asm volatile("cp.async.cg.shared.global [%0], [%1], 16;"
        :: "r"(dst), "l"(src) : "memory");
}
#define CP_COMMIT() asm volatile("cp.async.commit_group;" ::: "memory")
#define ONES2 0x3F803F80u

// ---------------- mask dtype detection (parallel) ---------------------------
__global__ void detect_mask_kernel(const unsigned char* __restrict__ m) {
    __shared__ int ok;
    if (threadIdx.x == 0) ok = 1;
    __syncthreads();
    const uint4 v = ((const uint4*)m)[threadIdx.x];
    uint32_t ww[4] = {v.x, v.y, v.z, v.w};
    bool bad = false;
    #pragma unroll
    for (int j = 0; j < 4; j++) bad |= (ww[j] > 1u);
    if (bad) ok = 0;
    __syncthreads();
    if (threadIdx.x == 0) g_mask_is_i32 = ok;
}

// -------- unified prep: maskbits + edge_x conv + weight conv ---------------
#define PREP_X0 NMASKW
#define PREP_W0 (NMASKW + ROWS * D_)
#define PREP_N  (PREP_W0 + 3 * D_ * D_ + 2 * D_ * D_)
__global__ void prep_kernel(const void* __restrict__ mask_in,
                            const float* __restrict__ edge_x,
                            const float* __restrict__ wq,
                            const float* __restrict__ w1,
                            const float* __restrict__ w2) {
    int i = blockIdx.x * blockDim.x + threadIdx.x;
    if (i < NMASKW) {
        uint32_t bits = 0;
        if (g_mask_is_i32) {
            const int* p = (const int*)mask_in + (size_t)i * 32;
            #pragma unroll
            for (int j = 0; j < 32; j++) bits |= (p[j] != 0 ? 1u : 0u) << j;
        } else {
            const uint4* p = (const uint4*)((const uint8_t*)mask_in + (size_t)i * 32);
            uint4 a = p[0], bq = p[1];
            uint32_t ww[8] = {a.x, a.y, a.z, a.w, bq.x, bq.y, bq.z, bq.w};
            #pragma unroll
            for (int u = 0; u < 8; u++)
                #pragma unroll
                for (int j = 0; j < 4; j++)
                    bits |= (((ww[u] >> (8 * j)) & 0xFFu) ? 1u : 0u) << (u * 4 + j);
        }
        g_maskbits[i] = bits;
    } else if (i < PREP_W0) {
        int j = i - PREP_X0;
        float f = edge_x[j];
        float h = bfr(f);
        g_xh[j] = __float2bfloat16_rn(h);
        g_xl[j] = __float2bfloat16_rn(f - h);
    } else if (i < PREP_N) {
        int j = i - PREP_W0;
        const float* src; __nv_bfloat16 *dh, *dl;
        if (j < 49152)      { src = wq; dh = g_wqh; dl = g_wql; }
        else if (j < 65536) { src = w1; dh = g_w1h; dl = g_w1l; j -= 49152; }
        else                { src = w2; dh = g_w2h; dl = g_w2l; j -= 65536; }
        float f = src[j];
        float h = bfr(f);
        dh[j] = __float2bfloat16_rn(h);
        dl[j] = __float2bfloat16_rn(f - h);
    }
}

// ===== QKV GEMM: BM=64, 2-stage khalf-pipelined cp.async staging ===========
#define QKV_SA 0u
#define QKV_SB 32768u
#define QKV_SMEM (96 * 1024)
__global__ __launch_bounds__(256) void qkv_gemm_kernel(const float* __restrict__ bias)
{
    extern __shared__ __align__(16) uint8_t dsm[];
    const uint32_t sbase = smem_u32(dsm);

    const int tid  = threadIdx.x;
    const int lane = tid & 31;
    const int w    = tid >> 5;
    const int wm   = w & 3;
    const int wn   = w >> 2;
    const int m0   = blockIdx.y * 64;
    const int n0   = blockIdx.x * 128;

    const int rq = lane >> 2;
    const int d0 = (lane & 3) * 2;
    const int lr16  = lane & 15;
    const int lclog = lane >> 4;
    const int lm = lane >> 3, lr = lane & 7;

    #pragma unroll
    for (int kh = 0; kh < 2; ++kh) {
        #pragma unroll
        for (int rep = 0; rep < 4; ++rep) {
            int idx = rep * 256 + tid;
            int plane = idx >> 9, row = (idx >> 3) & 63, chunk = idx & 7;
            const __nv_bfloat16* src = (plane ? g_xl : g_xh)
                + (size_t)(m0 + row) * 128 + kh * 64 + chunk * 8;
            uint32_t dst = sbase + QKV_SA + (uint32_t)(plane * 16384 + kh * 8192 + row * 128
                         + (((chunk ^ (row & 7))) << 4));
            cp16(dst, src);
        }
        #pragma unroll
        for (int rep = 0; rep < 8; ++rep) {
            int idx = rep * 256 + tid;
            int plane = idx >> 10, nh = (idx >> 9) & 1, kr0 = (idx >> 3) & 63, chunk = idx & 7;
            int kr = kh * 64 + kr0;
            const __nv_bfloat16* src = (plane ? g_wql : g_wqh)
                + (size_t)kr * (3 * D_) + n0 + nh * 64 + chunk * 8;
            uint32_t dst = sbase + QKV_SB + (uint32_t)(plane * 32768 + nh * 16384 + kr * 128
                         + (((chunk ^ (kr & 7))) << 4));
            cp16(dst, src);
        }
        CP_COMMIT();
    }

    float c[8][4];
    #pragma unroll
    for (int i = 0; i < 8; i++)
        #pragma unroll
        for (int j = 0; j < 4; j++) c[i][j] = 0.f;

    const int rowA = wm * 16 + lr16;
    #pragma unroll
    for (int kh = 0; kh < 2; ++kh) {
        if (kh == 0) asm volatile("cp.async.wait_group 1;" ::: "memory");
        else         asm volatile("cp.async.wait_group 0;" ::: "memory");
        __syncthreads();
        #pragma unroll
        for (int sl = 0; sl < 4; ++sl) {
            const int s = kh * 4 + sl;
            uint32_t ah[4], al[4];
            {
                uint32_t off = QKV_SA + (uint32_t)(kh * 8192 + rowA * 128
                             + ((((sl * 2 + lclog) ^ (rowA & 7))) << 4));
                ldm_x4(ah, sbase + off);
                ldm_x4(al, sbase + off + 16384);
            }
            int rowB = s * 16 + ((lm & 1) << 3) + lr;
            uint32_t rbase = QKV_SB + (uint32_t)(wn * 16384 + rowB * 128);
            #pragma unroll
            for (int g = 0; g < 4; ++g) {
                uint32_t chunk = (uint32_t)(g * 2 + (lm >> 1));
                uint32_t off = rbase + ((chunk ^ (rowB & 7)) << 4);
                uint32_t bh[4], bl[4];
                ldm_x4_t(bh, sbase + off);
                ldm_x4_t(bl, sbase + off + 32768);
                mma_bf16(c[g*2],   ah, bh[0], bh[1]);
                mma_bf16(c[g*2],   ah, bl[0], bl[1]);
                mma_bf16(c[g*2],   al, bh[0], bh[1]);
                mma_bf16(c[g*2+1], ah, bh[2], bh[3]);
                mma_bf16(c[g*2+1], ah, bl[2], bl[3]);
                mma_bf16(c[g*2+1], al, bh[2], bh[3]);
            }
        }
    }

    const int rowO = m0 + wm * 16 + rq;
    const float qscale = 0.25f * 1.44269504088896f;
    #pragma unroll
    for (int t8 = 0; t8 < 8; ++t8) {
        int col = n0 + wn * 64 + t8 * 8 + d0;
        float b0 = bias[col], b1 = bias[col + 1];
        float v00 = c[t8][0] + b0, v01 = c[t8][1] + b1;
        float v10 = c[t8][2] + b0, v11 = c[t8][3] + b1;

        if (n0 == 0) {
            *(float2*)(g_q + (size_t)rowO * 128 + col)       = make_float2(v00 * qscale, v01 * qscale);
            *(float2*)(g_q + (size_t)(rowO + 8) * 128 + col) = make_float2(v10 * qscale, v11 * qscale);
        } else if (n0 == 128) {
            int kc = col - 128;
            float h00 = bfr(v00), h01 = bfr(v01), h10 = bfr(v10), h11 = bfr(v11);
            ((uint32_t*)g_kh)[((size_t)rowO * 128 + kc) >> 1]       = pack_bf16x2(h00, h01);
            ((uint32_t*)g_kl)[((size_t)rowO * 128 + kc) >> 1]       = pack_bf16x2(v00 - h00, v01 - h01);
            ((uint32_t*)g_kh)[((size_t)(rowO + 8) * 128 + kc) >> 1] = pack_bf16x2(h10, h11);
            ((uint32_t*)g_kl)[((size_t)(rowO + 8) * 128 + kc) >> 1] = pack_bf16x2(v10 - h10, v11 - h11);
        } else {
            int vc = col - 256;
            ((uint32_t*)g_vh)[((size_t)rowO * 128 + vc) >> 1]       = pack_bf16x2(bfr(v00), bfr(v01));
            ((uint32_t*)g_vh)[((size_t)(rowO + 8) * 128 + vc) >> 1] = pack_bf16x2(bfr(v10), bfr(v11));
        }
    }
}

// ====== HMMA flash attention: 4 warps, NT=2, full keys, 3-buffer cp.async ==
#define KROWB 48
#define CHUNKB (128 * KROWB)
#define BUFB   (3 * CHUNKB)

__device__ __forceinline__ void attn_stage(uint32_t sbase, int buf, int c0,
                                           int b, int h, int tid) {
    const uint32_t dbase = sbase + (uint32_t)buf * BUFB;
    const size_t src = (size_t)(b * L_ + c0 + tid) * D_ + h * HD_;
    uint32_t dk = dbase + (uint32_t)(tid * KROWB);
    cp16(dk,                    g_kh + src);
    cp16(dk + 16,               g_kh + src + 8);
    cp16(dk + CHUNKB,           g_kl + src);
    cp16(dk + CHUNKB + 16,      g_kl + src + 8);
    cp16(dk + 2 * CHUNKB,       g_vh + src);
    cp16(dk + 2 * CHUNKB + 16,  g_vh + src + 8);
}

__global__ __launch_bounds__(128) void attn_mma_kernel(float* __restrict__ ctx)
{
    __shared__ __align__(16) uint8_t sKV[3 * BUFB];   // 54 KB (3 buffers)

    const int tid  = threadIdx.x;
    const int lane = tid & 31;
    const int w    = tid >> 5;
    const int b    = blockIdx.y >> 3;
    const int h    = blockIdx.y & 7;
    const int q0   = blockIdx.x << 7;

    const int rq = lane >> 2;
    const int d0 = (lane & 3) * 2;

    const uint32_t sbase = smem_u32(sKV);

    uint32_t ah[2][4], al[2][4];
    #pragma unroll
    for (int t = 0; t < 2; t++) {
        int rowA = q0 + w * 32 + t * 16 + rq;
        const float* qb = g_q + (size_t)(b * L_ + rowA) * D_ + h * HD_;
        float2 e0 = *(const float2*)(qb + d0);
        float2 e1 = *(const float2*)(qb + (size_t)8 * D_ + d0);
        float2 e2 = *(const float2*)(qb + d0 + 8);
        float2 e3 = *(const float2*)(qb + (size_t)8 * D_ + d0 + 8);
        float v[8] = {e0.x, e0.y, e1.x, e1.y, e2.x, e2.y, e3.x, e3.y};
        #pragma unroll
        for (int j = 0; j < 4; j++) {
            float hx = bfr(v[2*j]), hy = bfr(v[2*j+1]);
            ah[t][j] = pack_bf16x2(hx, hy);
            al[t][j] = pack_bf16x2(v[2*j] - hx, v[2*j+1] - hy);
        }
    }

    const uint4* mbase = (const uint4*)g_maskbits;
    int mrowA[2], mrowB[2];
    #pragma unroll
    for (int t = 0; t < 2; t++) {
        mrowA[t] = (b * L_ + q0 + w * 32 + t * 16 + rq) * 8;
        mrowB[t] = mrowA[t] + 8 * 8;
    }

    const int lm = lane >> 3, lr = lane & 7;
    const uint32_t kOff = (uint32_t)((((lm >> 1) << 3) + lr) * KROWB + ((lm & 1) << 4));
    const uint32_t vOff = (uint32_t)((((lm & 1) << 3) + lr) * KROWB + ((lm >> 1) << 4));

    float o[2][2][4];
    float lac[2][4];
    #pragma unroll
    for (int t = 0; t < 2; t++) {
        #pragma unroll
        for (int n = 0; n < 2; n++)
            #pragma unroll
            for (int i = 0; i < 4; i++) o[t][n][i] = 0.f;
        #pragma unroll
        for (int i = 0; i < 4; i++) lac[t][i] = 0.f;
    }

    attn_stage(sbase, 0, 0, b, h, tid);
    CP_COMMIT();

    int buf = 0;
    for (int ck = 0; ck < 8; ++ck) {
        if (ck < 7) {
            int nbuf = buf + 1; if (nbuf == 3) nbuf = 0;
            attn_stage(sbase, nbuf, (ck + 1) << 7, b, h, tid);
            CP_COMMIT();
            asm volatile("cp.async.wait_group 1;" ::: "memory");
        } else {
            asm volatile("cp.async.wait_group 0;" ::: "memory");
        }
        __syncthreads();

        const uint32_t aKh = sbase + (uint32_t)buf * BUFB + kOff;
        const uint32_t aKl = aKh + CHUNKB;
        const uint32_t aVh = sbase + (uint32_t)buf * BUFB + 2 * CHUNKB + vOff;

        uint32_t mwa[2][4], mwb[2][4];
        #pragma unroll
        for (int t = 0; t < 2; t++) {
            uint4 a = mbase[mrowA[t] + ck];
            uint4 bq = mbase[mrowB[t] + ck];
            mwa[t][0] = a.x;  mwa[t][1] = a.y;  mwa[t][2] = a.z;  mwa[t][3] = a.w;
            mwb[t][0] = bq.x; mwb[t][1] = bq.y; mwb[t][2] = bq.z; mwb[t][3] = bq.w;
        }

        #pragma unroll
        for (int s = 0; s < 8; ++s) {
            const uint32_t so = (uint32_t)(s * 16 * KROWB);
            uint32_t kh[4], kl[4], vh[4];
            ldm_x4(kh, aKh + so);
            ldm_x4(kl, aKl + so);
            ldm_x4_t(vh, aVh + so);
            const int sh = ((s & 1) << 4) + d0;

            #pragma unroll
            for (int t = 0; t < 2; t++) {
                float cA0[4] = {0.f, 0.f, 0.f, 0.f};
                float cB0[4] = {0.f, 0.f, 0.f, 0.f};
                float cA1[4] = {0.f, 0.f, 0.f, 0.f};
                float cB1[4] = {0.f, 0.f, 0.f, 0.f};
                mma_bf16(cA0, ah[t], kh[0], kh[1]);
                mma_bf16(cB0, ah[t], kl[0], kl[1]);
                mma_bf16(cA1, ah[t], kh[2], kh[3]);
                mma_bf16(cB1, ah[t], kl[2], kl[3]);
                mma_bf16(cB0, al[t], kh[0], kh[1]);
                mma_bf16(cB1, al[t], kh[2], kh[3]);

                uint32_t wa = mwa[t][s >> 1] >> sh;
                uint32_t wb = mwb[t][s >> 1] >> sh;

                float p00 = (wa & 1u)     ? 0.f : ex2f(cA0[0] + cB0[0]);
                float p01 = (wa & 2u)     ? 0.f : ex2f(cA0[1] + cB0[1]);
                float p02 = (wb & 1u)     ? 0.f : ex2f(cA0[2] + cB0[2]);
                float p03 = (wb & 2u)     ? 0.f : ex2f(cA0[3] + cB0[3]);
                float p10 = (wa & 0x100u) ? 0.f : ex2f(cA1[0] + cB1[0]);
                float p11 = (wa & 0x200u) ? 0.f : ex2f(cA1[1] + cB1[1]);
                float p12 = (wb & 0x100u) ? 0.f : ex2f(cA1[2] + cB1[2]);
                float p13 = (wb & 0x200u) ? 0.f : ex2f(cA1[3] + cB1[3]);

                uint32_t ap[4];
                ap[0] = pack_bf16x2(p00, p01);
                ap[1] = pack_bf16x2(p02, p03);
                ap[2] = pack_bf16x2(p10, p11);
                ap[3] = pack_bf16x2(p12, p13);

                mma_bf16(o[t][0], ap, vh[0], vh[1]);
                mma_bf16(o[t][1], ap, vh[2], vh[3]);
                mma_bf16(lac[t], ap, ONES2, ONES2);
            }
        }
        // no trailing sync: 3-buffer rotation + post-wait barrier order reuse
        buf = buf + 1; if (buf == 3) buf = 0;
    }

    #pragma unroll
    for (int t = 0; t < 2; t++) {
        float ia = (lac[t][0] > 0.f) ? (1.f / lac[t][0]) : 0.f;
        float ib = (lac[t][2] > 0.f) ? (1.f / lac[t][2]) : 0.f;
        int rowA = q0 + w * 32 + t * 16 + rq;
        float* oA = ctx + (size_t)(b * L_ + rowA) * D_ + h * HD_;
        float* oB = oA + (size_t)8 * D_;
        #pragma unroll
        for (int n = 0; n < 2; n++) {
            *(float2*)(oA + n * 8 + d0) = make_float2(o[t][n][0] * ia, o[t][n][1] * ia);
            *(float2*)(oB + n * 8 + d0) = make_float2(o[t][n][2] * ib, o[t][n][3] * ib);
        }
    }
}

// -------- residual add + LayerNorm -> hi/lo planes (2 rows per block) ------
__global__ __launch_bounds__(256) void add_ln_kernel(
    const float* __restrict__ xin, const float* __restrict__ r,
    const float* __restrict__ gamma, const float* __restrict__ beta,
    __nv_bfloat16* __restrict__ oh, __nv_bfloat16* __restrict__ ol)
{
    const int half = threadIdx.x >> 7;
    const int t    = threadIdx.x & 127;
    const int row  = blockIdx.x * 2 + half;
    const int warp = threadIdx.x >> 5, lane = threadIdx.x & 31;
    __shared__ float red1[8], red2[8];

    float v = xin[(size_t)row * D_ + t] + r[(size_t)row * D_ + t];

    float s = v;
    #pragma unroll
    for (int o = 16; o; o >>= 1) s += __shfl_xor_sync(0xffffffffu, s, o);
    if (lane == 0) red1[warp] = s;
    __syncthreads();
    const int wb = half * 4;
    float mu = (red1[wb] + red1[wb+1] + red1[wb+2] + red1[wb+3]) * (1.f / D_);

    float c = v - mu;
    float q = c * c;
    #pragma unroll
    for (int o = 16; o; o >>= 1) q += __shfl_xor_sync(0xffffffffu, q, o);
    if (lane == 0) red2[warp] = q;
    __syncthreads();
    float var = (red2[wb] + red2[wb+1] + red2[wb+2] + red2[wb+3]) * (1.f / D_);

    float y = c * rsqrtf(var + LN_EPS) * gamma[t] + beta[t];
    float hy = bfr(y);
    oh[(size_t)row * D_ + t] = __float2bfloat16_rn(hy);
    ol[(size_t)row * D_ + t] = __float2bfloat16_rn(y - hy);
}

// ====== fused FFN BM=128, 512 thr, single wave (grid=128) ===================
#define FFN_SA  0u
#define FFN_SW1 65536u
#define FFN_SW2 131072u
#define FFN_SMEM (192 * 1024)
__global__ __launch_bounds__(512) void hmma_ffn_ln(
    const float* __restrict__ b1, const float* __restrict__ b2,
    const float* __restrict__ gamma, const float* __restrict__ beta,
    float* __restrict__ out)
{
    extern __shared__ __align__(16) uint8_t dsm[];
    const uint32_t sbase = smem_u32(dsm);

    const int tid  = threadIdx.x;
    const int lane = tid & 31;
    const int w    = tid >> 5;
    const int wm   = w & 7;
    const int wn   = w >> 3;
    const int m0   = blockIdx.x * 128;

    const int rq = lane >> 2;
    const int d0 = (lane & 3) * 2;
    const int lr16  = lane & 15;
    const int lclog = lane >> 4;
    const int lm = lane >> 3, lr = lane & 7;

    #pragma unroll
    for (int rep = 0; rep < 8; ++rep) {
        int idx = rep * 512 + tid;
        int plane = idx >> 11, kh = (idx >> 10) & 1, row = (idx >> 3) & 127, chunk = idx & 7;
        const __nv_bfloat16* src = (plane ? g_x1l : g_x1h)
            + (size_t)(m0 + row) * 128 + kh * 64 + chunk * 8;
        uint32_t dst = sbase + FFN_SA + (uint32_t)(plane * 32768 + kh * 16384 + row * 128
                     + (((chunk ^ (row & 7))) << 4));
        cp16(dst, src);
    }
    #pragma unroll
    for (int rep = 0; rep < 8; ++rep) {
        int idx = rep * 512 + tid;
        int plane = idx >> 11, nh = (idx >> 10) & 1, kr = (idx >> 3) & 127, chunk = idx & 7;
        const __nv_bfloat16* src = (plane ? g_w1l : g_w1h)
            + (size_t)kr * 128 + nh * 64 + chunk * 8;
        uint32_t dst = sbase + FFN_SW1 + (uint32_t)(plane * 32768 + nh * 16384 + kr * 128
                     + (((chunk ^ (kr & 7))) << 4));
        cp16(dst, src);
    }
    CP_COMMIT();
    #pragma unroll
    for (int rep = 0; rep < 8; ++rep) {
        int idx = rep * 512 + tid;
        int plane = idx >> 11, nh = (idx >> 10) & 1, kr = (idx >> 3) & 127, chunk = idx & 7;
        const __nv_bfloat16* src = (plane ? g_w2l : g_w2h)
            + (size_t)kr * 128 + nh * 64 + chunk * 8;
        uint32_t dst = sbase + FFN_SW2 + (uint32_t)(plane * 32768 + nh * 16384 + kr * 128
                     + (((chunk ^ (kr & 7))) << 4));
        cp16(dst, src);
    }
    CP_COMMIT();

    float c[8][4];
    #pragma unroll
    for (int i = 0; i < 8; i++)
        #pragma unroll
        for (int j = 0; j < 4; j++) c[i][j] = 0.f;

    asm volatile("cp.async.wait_group 1;" ::: "memory");
    __syncthreads();

    const int rowA = wm * 16 + lr16;
    // GEMM1: T = relu(x1 @ w1 + b1)
    #pragma unroll
    for (int s = 0; s < 8; ++s) {
        const int kh = s >> 2, sl = s & 3;
        uint32_t ah[4], al[4];
        {
            uint32_t off = FFN_SA + (uint32_t)(kh * 16384 + rowA * 128
                         + ((((sl * 2 + lclog) ^ (rowA & 7))) << 4));
            ldm_x4(ah, sbase + off);
            ldm_x4(al, sbase + off + 32768);
        }
        int rowB = s * 16 + ((lm & 1) << 3) + lr;
        uint32_t rbase = FFN_SW1 + (uint32_t)(wn * 16384 + rowB * 128);
        #pragma unroll
        for (int g = 0; g < 4; ++g) {
            uint32_t chunk = (uint32_t)(g * 2 + (lm >> 1));
            uint32_t off = rbase + ((chunk ^ (rowB & 7)) << 4);
            uint32_t bh[4], bl[4];
            ldm_x4_t(bh, sbase + off);
            ldm_x4_t(bl, sbase + off + 32768);
            mma_bf16(c[g*2],   ah, bh[0], bh[1]);
            mma_bf16(c[g*2],   ah, bl[0], bl[1]);
            mma_bf16(c[g*2],   al, bh[0], bh[1]);
            mma_bf16(c[g*2+1], ah, bh[2], bh[3]);
            mma_bf16(c[g*2+1], ah, bl[2], bl[3]);
            mma_bf16(c[g*2+1], al, bh[2], bh[3]);
        }
    }

    __syncthreads();
    {
        const int rowT = wm * 16 + rq;
        #pragma unroll
        for (int t8 = 0; t8 < 8; ++t8) {
            int col = wn * 64 + t8 * 8 + d0;
            float bb0 = b1[col], bb1 = b1[col + 1];
            float v00 = fmaxf(c[t8][0] + bb0, 0.f), v01 = fmaxf(c[t8][1] + bb1, 0.f);
            float v10 = fmaxf(c[t8][2] + bb0, 0.f), v11 = fmaxf(c[t8][3] + bb1, 0.f);
            float h00 = bfr(v00), h01 = bfr(v01), h10 = bfr(v10), h11 = bfr(v11);
            uint32_t off0 = FFN_SA + (uint32_t)(wn * 16384 + rowT * 128
                          + (((t8 ^ (rowT & 7))) << 4) + d0 * 2);
            uint32_t off1 = FFN_SA + (uint32_t)(wn * 16384 + (rowT + 8) * 128
                          + (((t8 ^ ((rowT + 8) & 7))) << 4) + d0 * 2);
            *(uint32_t*)(dsm + off0)           = pack_bf16x2(h00, h01);
            *(uint32_t*)(dsm + off0 + 32768)   = pack_bf16x2(v00 - h00, v01 - h01);
            *(uint32_t*)(dsm + off1)           = pack_bf16x2(h10, h11);
            *(uint32_t*)(dsm + off1 + 32768)   = pack_bf16x2(v10 - h10, v11 - h11);
        }
    }
    asm volatile("cp.async.wait_group 0;" ::: "memory");
    __syncthreads();

    // GEMM2: Y = T @ w2
    #pragma unroll
    for (int i = 0; i < 8; i++)
        #pragma unroll
        for (int j = 0; j < 4; j++) c[i][j] = 0.f;

    #pragma unroll
    for (int s = 0; s < 8; ++s) {
        const int kh = s >> 2, sl = s & 3;
        uint32_t ah[4], al[4];
        {
            uint32_t off = FFN_SA + (uint32_t)(kh * 16384 + rowA * 128
                         + ((((sl * 2 + lclog) ^ (rowA & 7))) << 4));
            ldm_x4(ah, sbase + off);
            ldm_x4(al, sbase + off + 32768);
        }
        int rowB = s * 16 + ((lm & 1) << 3) + lr;
        uint32_t rbase = FFN_SW2 + (uint32_t)(wn * 16384 + rowB * 128);
        #pragma unroll
        for (int g = 0; g < 4; ++g) {
            uint32_t chunk = (uint32_t)(g * 2 + (lm >> 1));
            uint32_t off = rbase + ((chunk ^ (rowB & 7)) << 4);
            uint32_t bh[4], bl[4];
            ldm_x4_t(bh, sbase + off);
            ldm_x4_t(bl, sbase + off + 32768);
            mma_bf16(c[g*2],   ah, bh[0], bh[1]);
            mma_bf16(c[g*2],   ah, bl[0], bl[1]);
            mma_bf16(c[g*2],   al, bh[0], bh[1]);
            mma_bf16(c[g*2+1], ah, bh[2], bh[3]);
            mma_bf16(c[g*2+1], ah, bl[2], bl[3]);
            mma_bf16(c[g*2+1], al, bh[2], bh[3]);
        }
    }

    __syncthreads();
    float* sC = (float*)(dsm + FFN_SW1);
    {
        const int rowT = wm * 16 + rq;
        #pragma unroll
        for (int t8 = 0; t8 < 8; ++t8) {
            int col = wn * 64 + t8 * 8 + d0;
            float bb0 = b2[col], bb1 = b2[col + 1];
            sC[rowT * 128 + col]           = c[t8][0] + bb0;
            sC[rowT * 128 + col + 1]       = c[t8][1] + bb1;
            sC[(rowT + 8) * 128 + col]     = c[t8][2] + bb0;
            sC[(rowT + 8) * 128 + col + 1] = c[t8][3] + bb1;
        }
    }
    __syncthreads();

    {
        const int row = tid >> 2;
        const int q4 = tid & 3;
        float* vr = sC + row * 128 + q4 * 32;
        const __nv_bfloat16* xh = g_x1h + (size_t)(m0 + row) * 128 + q4 * 32;
        const __nv_bfloat16* xl = g_x1l + (size_t)(m0 + row) * 128 + q4 * 32;

        float s = 0.f;
        #pragma unroll
        for (int j = 0; j < 32; j++) {
            float x = __bfloat162float(xh[j]) + __bfloat162float(xl[j]);
            float v = vr[j] + x;
            vr[j] = v;
            s += v;
        }
        s += __shfl_xor_sync(0xffffffffu, s, 1);
        s += __shfl_xor_sync(0xffffffffu, s, 2);
        float mu = s * (1.f / 128.f);

        float q = 0.f;
        #pragma unroll
        for (int j = 0; j < 32; j++) {
            float d = vr[j] - mu;
            q += d * d;
        }
        q += __shfl_xor_sync(0xffffffffu, q, 1);
        q += __shfl_xor_sync(0xffffffffu, q, 2);
        float rs = rsqrtf(q * (1.f / 128.f) + LN_EPS);

        float* orow = out + (size_t)(m0 + row) * 128 + q4 * 32;
        #pragma unroll
        for (int j = 0; j < 32; j++) {
            orow[j] = (vr[j] - mu) * rs * gamma[q4 * 32 + j] + beta[q4 * 32 + j];
        }
    }
}

// ---------------- launch --------------------------------------------------
extern "C" void kernel_launch(void* const* d_in, const int* in_sizes, int n_in,
                              void* d_out, int out_size)
{
    const float* edge_x    = (const float*)d_in[0];
    const void*  edge_mask = d_in[1];
    const float* in_proj_w = (const float*)d_in[2];
    const float* in_proj_b = (const float*)d_in[3];
    const float* w1        = (const float*)d_in[4];
    const float* b1        = (const float*)d_in[5];
    const float* w2        = (const float*)d_in[6];
    const float* b2        = (const float*)d_in[7];
    const float* g1        = (const float*)d_in[8];
    const float* beta1     = (const float*)d_in[9];
    const float* g2        = (const float*)d_in[10];
    const float* beta2     = (const float*)d_in[11];
    float* out = (float*)d_out;

    cudaFuncSetAttribute(qkv_gemm_kernel, cudaFuncAttributeMaxDynamicSharedMemorySize, QKV_SMEM);
    cudaFuncSetAttribute(hmma_ffn_ln,     cudaFuncAttributeMaxDynamicSharedMemorySize, FFN_SMEM);

    void *p_ctx, *p_x1h, *p_x1l;
    cudaGetSymbolAddress(&p_ctx, g_ctx);
    cudaGetSymbolAddress(&p_x1h, g_x1h);
    cudaGetSymbolAddress(&p_x1l, g_x1l);

    // 0) mask dtype detect (parallel)
    detect_mask_kernel<<<1, 256>>>((const unsigned char*)edge_mask);

    // 1) unified prep
    prep_kernel<<<(PREP_N + 255) / 256, 256>>>(edge_mask, edge_x, in_proj_w, w1, w2);

    // 2) QKV projection
    {
        dim3 grid(3, ROWS / 64);
        qkv_gemm_kernel<<<grid, 256, QKV_SMEM>>>(in_proj_b);
    }

    // 3) masked attention -> normalized ctx (R14 body, 3-buffer, no tail sync)
    {
        dim3 grid(L_ / 128, B_ * H_);
        attn_mma_kernel<<<grid, 128>>>((float*)p_ctx);
    }

    // 4) x1 = LN(edge_x + ctx) -> hi/lo planes
    add_ln_kernel<<<ROWS / 2, 256>>>(edge_x, (const float*)p_ctx,
                                     g1, beta1,
                                     (__nv_bfloat16*)p_x1h, (__nv_bfloat16*)p_x1l);

    // 5) fused FFN (single wave)
    hmma_ffn_ln<<<ROWS / 128, 512, FFN_SMEM>>>(b1, b2, g2, beta2, out);
}

// round 17
// speedup vs baseline: 1.0953x; 1.0953x over previous
#include <cuda_runtime.h>
#include <cuda_bf16.h>
#include <math_constants.h>
#include <cstdint>

// Problem constants
#define B_   16
#define L_   1024
#define D_   128
#define H_   8
#define HD_  16
#define ROWS (B_ * L_)          // 16384
#define LN_EPS 1e-5f
#define NMASKW (B_ * L_ * L_ / 32)   // 524288

// ---------------- scratch (device globals) ---------------------------------
__device__ float g_q  [ROWS * D_];                 // Q fp32, PRE-SCALED
__device__ __nv_bfloat16 g_kh[ROWS * D_];
__device__ __nv_bfloat16 g_kl[ROWS * D_];
__device__ __nv_bfloat16 g_vh[ROWS * D_];
__device__ __nv_bfloat16 g_xh[ROWS * D_];
__device__ __nv_bfloat16 g_xl[ROWS * D_];
__device__ __nv_bfloat16 g_wqh[D_ * 3 * D_];
__device__ __nv_bfloat16 g_wql[D_ * 3 * D_];
__device__ __nv_bfloat16 g_w1h[D_ * D_];
__device__ __nv_bfloat16 g_w1l[D_ * D_];
__device__ __nv_bfloat16 g_w2h[D_ * D_];
__device__ __nv_bfloat16 g_w2l[D_ * D_];
__device__ __nv_bfloat16 g_x1h[ROWS * D_];
__device__ __nv_bfloat16 g_x1l[ROWS * D_];
__device__ float g_ctx[ROWS * D_];
__device__ uint32_t g_maskbits[NMASKW];
__device__ int g_mask_is_i32;

// ============================ helpers ======================================
__device__ __forceinline__ uint32_t smem_u32(const void* p) {
    uint32_t a;
    asm("{ .reg .u64 t; cvta.to.shared.u64 t, %1; cvt.u32.u64 %0, t; }"
        : "=r"(a) : "l"(p));
    return a;
}
__device__ __forceinline__ uint32_t pack_bf16x2(float e, float o) {
    uint32_t r;
    asm("cvt.rn.bf16x2.f32 %0, %1, %2;" : "=r"(r) : "f"(o), "f"(e));
    return r;
}
__device__ __forceinline__ float ex2f(float x) {
    float y; asm("ex2.approx.f32 %0, %1;" : "=f"(y) : "f"(x)); return y;
}
__device__ __forceinline__ float bfr(float x) {
    return __bfloat162float(__float2bfloat16_rn(x));
}
__device__ __forceinline__ void mma_bf16(float* c, const uint32_t* a, uint32_t b0, uint32_t b1) {
    asm volatile("mma.sync.aligned.m16n8k16.row.col.f32.bf16.bf16.f32 "
        "{%0,%1,%2,%3}, {%4,%5,%6,%7}, {%8,%9}, {%0,%1,%2,%3};"
        : "+f"(c[0]), "+f"(c[1]), "+f"(c[2]), "+f"(c[3])
        : "r"(a[0]), "r"(a[1]), "r"(a[2]), "r"(a[3]), "r"(b0), "r"(b1));
}
__device__ __forceinline__ void ldm_x4(uint32_t* r, uint32_t addr) {
    asm volatile("ldmatrix.sync.aligned.m8n8.x4.shared.b16 {%0,%1,%2,%3}, [%4];"
        : "=r"(r[0]), "=r"(r[1]), "=r"(r[2]), "=r"(r[3]) : "r"(addr));
}
__device__ __forceinline__ void ldm_x4_t(uint32_t* r, uint32_t addr) {
    asm volatile("ldmatrix.sync.aligned.m8n8.x4.trans.shared.b16 {%0,%1,%2,%3}, [%4];"
        : "=r"(r[0]), "=r"(r[1]), "=r"(r[2]), "=r"(r[3]) : "r"(addr));
}
__device__ __forceinline__ void cp16(uint32_t dst, const void* src) {
    asm volatile("cp.async.cg.shared.global [%0], [%1], 16;"
        :: "r"(dst), "l"(src) : "memory");
}
#define CP_COMMIT() asm volatile("cp.async.commit_group;" ::: "memory")
#define ONES2 0x3F803F80u

// ---------------- mask dtype detection (parallel) ---------------------------
__global__ void detect_mask_kernel(const unsigned char* __restrict__ m) {
    __shared__ int ok;
    if (threadIdx.x == 0) ok = 1;
    __syncthreads();
    const uint4 v = ((const uint4*)m)[threadIdx.x];
    uint32_t ww[4] = {v.x, v.y, v.z, v.w};
    bool bad = false;
    #pragma unroll
    for (int j = 0; j < 4; j++) bad |= (ww[j] > 1u);
    if (bad) ok = 0;
    __syncthreads();
    if (threadIdx.x == 0) g_mask_is_i32 = ok;
}

// -------- unified prep: maskbits + edge_x conv + weight conv ---------------
#define PREP_X0 NMASKW
#define PREP_W0 (NMASKW + ROWS * D_)
#define PREP_N  (PREP_W0 + 3 * D_ * D_ + 2 * D_ * D_)
__global__ void prep_kernel(const void* __restrict__ mask_in,
                            const float* __restrict__ edge_x,
                            const float* __restrict__ wq,
                            const float* __restrict__ w1,
                            const float* __restrict__ w2) {
    int i = blockIdx.x * blockDim.x + threadIdx.x;
    if (i < NMASKW) {
        uint32_t bits = 0;
        if (g_mask_is_i32) {
            const int* p = (const int*)mask_in + (size_t)i * 32;
            #pragma unroll
            for (int j = 0; j < 32; j++) bits |= (p[j] != 0 ? 1u : 0u) << j;
        } else {
            const uint4* p = (const uint4*)((const uint8_t*)mask_in + (size_t)i * 32);
            uint4 a = p[0], bq = p[1];
            uint32_t ww[8] = {a.x, a.y, a.z, a.w, bq.x, bq.y, bq.z, bq.w};
            #pragma unroll
            for (int u = 0; u < 8; u++)
                #pragma unroll
                for (int j = 0; j < 4; j++)
                    bits |= (((ww[u] >> (8 * j)) & 0xFFu) ? 1u : 0u) << (u * 4 + j);
        }
        g_maskbits[i] = bits;
    } else if (i < PREP_W0) {
        int j = i - PREP_X0;
        float f = edge_x[j];
        float h = bfr(f);
        g_xh[j] = __float2bfloat16_rn(h);
        g_xl[j] = __float2bfloat16_rn(f - h);
    } else if (i < PREP_N) {
        int j = i - PREP_W0;
        const float* src; __nv_bfloat16 *dh, *dl;
        if (j < 49152)      { src = wq; dh = g_wqh; dl = g_wql; }
        else if (j < 65536) { src = w1; dh = g_w1h; dl = g_w1l; j -= 49152; }
        else                { src = w2; dh = g_w2h; dl = g_w2l; j -= 65536; }
        float f = src[j];
        float h = bfr(f);
        dh[j] = __float2bfloat16_rn(h);
        dl[j] = __float2bfloat16_rn(f - h);
    }
}

// ===== QKV GEMM: BM=64, 2-stage khalf-pipelined cp.async staging ===========
#define QKV_SA 0u
#define QKV_SB 32768u
#define QKV_SMEM (96 * 1024)
__global__ __launch_bounds__(256) void qkv_gemm_kernel(const float* __restrict__ bias)
{
    extern __shared__ __align__(16) uint8_t dsm[];
    const uint32_t sbase = smem_u32(dsm);

    const int tid  = threadIdx.x;
    const int lane = tid & 31;
    const int w    = tid >> 5;
    const int wm   = w & 3;
    const int wn   = w >> 2;
    const int m0   = blockIdx.y * 64;
    const int n0   = blockIdx.x * 128;

    const int rq = lane >> 2;
    const int d0 = (lane & 3) * 2;
    const int lr16  = lane & 15;
    const int lclog = lane >> 4;
    const int lm = lane >> 3, lr = lane & 7;

    #pragma unroll
    for (int kh = 0; kh < 2; ++kh) {
        #pragma unroll
        for (int rep = 0; rep < 4; ++rep) {
            int idx = rep * 256 + tid;
            int plane = idx >> 9, row = (idx >> 3) & 63, chunk = idx & 7;
            const __nv_bfloat16* src = (plane ? g_xl : g_xh)
                + (size_t)(m0 + row) * 128 + kh * 64 + chunk * 8;
            uint32_t dst = sbase + QKV_SA + (uint32_t)(plane * 16384 + kh * 8192 + row * 128
                         + (((chunk ^ (row & 7))) << 4));
            cp16(dst, src);
        }
        #pragma unroll
        for (int rep = 0; rep < 8; ++rep) {
            int idx = rep * 256 + tid;
            int plane = idx >> 10, nh = (idx >> 9) & 1, kr0 = (idx >> 3) & 63, chunk = idx & 7;
            int kr = kh * 64 + kr0;
            const __nv_bfloat16* src = (plane ? g_wql : g_wqh)
                + (size_t)kr * (3 * D_) + n0 + nh * 64 + chunk * 8;
            uint32_t dst = sbase + QKV_SB + (uint32_t)(plane * 32768 + nh * 16384 + kr * 128
                         + (((chunk ^ (kr & 7))) << 4));
            cp16(dst, src);
        }
        CP_COMMIT();
    }

    float c[8][4];
    #pragma unroll
    for (int i = 0; i < 8; i++)
        #pragma unroll
        for (int j = 0; j < 4; j++) c[i][j] = 0.f;

    const int rowA = wm * 16 + lr16;
    #pragma unroll
    for (int kh = 0; kh < 2; ++kh) {
        if (kh == 0) asm volatile("cp.async.wait_group 1;" ::: "memory");
        else         asm volatile("cp.async.wait_group 0;" ::: "memory");
        __syncthreads();
        #pragma unroll
        for (int sl = 0; sl < 4; ++sl) {
            const int s = kh * 4 + sl;
            uint32_t ah[4], al[4];
            {
                uint32_t off = QKV_SA + (uint32_t)(kh * 8192 + rowA * 128
                             + ((((sl * 2 + lclog) ^ (rowA & 7))) << 4));
                ldm_x4(ah, sbase + off);
                ldm_x4(al, sbase + off + 16384);
            }
            int rowB = s * 16 + ((lm & 1) << 3) + lr;
            uint32_t rbase = QKV_SB + (uint32_t)(wn * 16384 + rowB * 128);
            #pragma unroll
            for (int g = 0; g < 4; ++g) {
                uint32_t chunk = (uint32_t)(g * 2 + (lm >> 1));
                uint32_t off = rbase + ((chunk ^ (rowB & 7)) << 4);
                uint32_t bh[4], bl[4];
                ldm_x4_t(bh, sbase + off);
                ldm_x4_t(bl, sbase + off + 32768);
                mma_bf16(c[g*2],   ah, bh[0], bh[1]);
                mma_bf16(c[g*2],   ah, bl[0], bl[1]);
                mma_bf16(c[g*2],   al, bh[0], bh[1]);
                mma_bf16(c[g*2+1], ah, bh[2], bh[3]);
                mma_bf16(c[g*2+1], ah, bl[2], bl[3]);
                mma_bf16(c[g*2+1], al, bh[2], bh[3]);
            }
        }
    }

    const int rowO = m0 + wm * 16 + rq;
    const float qscale = 0.25f * 1.44269504088896f;
    #pragma unroll
    for (int t8 = 0; t8 < 8; ++t8) {
        int col = n0 + wn * 64 + t8 * 8 + d0;
        float b0 = bias[col], b1 = bias[col + 1];
        float v00 = c[t8][0] + b0, v01 = c[t8][1] + b1;
        float v10 = c[t8][2] + b0, v11 = c[t8][3] + b1;

        if (n0 == 0) {
            *(float2*)(g_q + (size_t)rowO * 128 + col)       = make_float2(v00 * qscale, v01 * qscale);
            *(float2*)(g_q + (size_t)(rowO + 8) * 128 + col) = make_float2(v10 * qscale, v11 * qscale);
        } else if (n0 == 128) {
            int kc = col - 128;
            float h00 = bfr(v00), h01 = bfr(v01), h10 = bfr(v10), h11 = bfr(v11);
            ((uint32_t*)g_kh)[((size_t)rowO * 128 + kc) >> 1]       = pack_bf16x2(h00, h01);
            ((uint32_t*)g_kl)[((size_t)rowO * 128 + kc) >> 1]       = pack_bf16x2(v00 - h00, v01 - h01);
            ((uint32_t*)g_kh)[((size_t)(rowO + 8) * 128 + kc) >> 1] = pack_bf16x2(h10, h11);
            ((uint32_t*)g_kl)[((size_t)(rowO + 8) * 128 + kc) >> 1] = pack_bf16x2(v10 - h10, v11 - h11);
        } else {
            int vc = col - 256;
            ((uint32_t*)g_vh)[((size_t)rowO * 128 + vc) >> 1]       = pack_bf16x2(bfr(v00), bfr(v01));
            ((uint32_t*)g_vh)[((size_t)(rowO + 8) * 128 + vc) >> 1] = pack_bf16x2(bfr(v10), bfr(v11));
        }
    }
}

// ============ HMMA flash attention: 4 warps, NT=2, full keys, cp.async =====
#define KROWB 48
#define CHUNKB (128 * KROWB)
#define BUFB   (3 * CHUNKB)

__device__ __forceinline__ void attn_stage(uint32_t sbase, int buf, int c0,
                                           int b, int h, int tid) {
    const uint32_t dbase = sbase + (uint32_t)buf * BUFB;
    const size_t src = (size_t)(b * L_ + c0 + tid) * D_ + h * HD_;
    uint32_t dk = dbase + (uint32_t)(tid * KROWB);
    cp16(dk,                    g_kh + src);
    cp16(dk + 16,               g_kh + src + 8);
    cp16(dk + CHUNKB,           g_kl + src);
    cp16(dk + CHUNKB + 16,      g_kl + src + 8);
    cp16(dk + 2 * CHUNKB,       g_vh + src);
    cp16(dk + 2 * CHUNKB + 16,  g_vh + src + 8);
}

__global__ __launch_bounds__(128) void attn_mma_kernel(float* __restrict__ ctx)
{
    __shared__ __align__(16) uint8_t sKV[2 * BUFB];   // 36 KB

    const int tid  = threadIdx.x;
    const int lane = tid & 31;
    const int w    = tid >> 5;
    const int b    = blockIdx.y >> 3;
    const int h    = blockIdx.y & 7;
    const int q0   = blockIdx.x << 7;

    const int rq = lane >> 2;
    const int d0 = (lane & 3) * 2;

    const uint32_t sbase = smem_u32(sKV);

    uint32_t ah[2][4], al[2][4];
    #pragma unroll
    for (int t = 0; t < 2; t++) {
        int rowA = q0 + w * 32 + t * 16 + rq;
        const float* qb = g_q + (size_t)(b * L_ + rowA) * D_ + h * HD_;
        float2 e0 = *(const float2*)(qb + d0);
        float2 e1 = *(const float2*)(qb + (size_t)8 * D_ + d0);
        float2 e2 = *(const float2*)(qb + d0 + 8);
        float2 e3 = *(const float2*)(qb + (size_t)8 * D_ + d0 + 8);
        float v[8] = {e0.x, e0.y, e1.x, e1.y, e2.x, e2.y, e3.x, e3.y};
        #pragma unroll
        for (int j = 0; j < 4; j++) {
            float hx = bfr(v[2*j]), hy = bfr(v[2*j+1]);
            ah[t][j] = pack_bf16x2(hx, hy);
            al[t][j] = pack_bf16x2(v[2*j] - hx, v[2*j+1] - hy);
        }
    }

    const uint4* mbase = (const uint4*)g_maskbits;
    int mrowA[2], mrowB[2];
    #pragma unroll
    for (int t = 0; t < 2; t++) {
        mrowA[t] = (b * L_ + q0 + w * 32 + t * 16 + rq) * 8;
        mrowB[t] = mrowA[t] + 8 * 8;
    }

    const int lm = lane >> 3, lr = lane & 7;
    const uint32_t kOff = (uint32_t)((((lm >> 1) << 3) + lr) * KROWB + ((lm & 1) << 4));
    const uint32_t vOff = (uint32_t)((((lm & 1) << 3) + lr) * KROWB + ((lm >> 1) << 4));

    float o[2][2][4];
    float lac[2][4];
    #pragma unroll
    for (int t = 0; t < 2; t++) {
        #pragma unroll
        for (int n = 0; n < 2; n++)
            #pragma unroll
            for (int i = 0; i < 4; i++) o[t][n][i] = 0.f;
        #pragma unroll
        for (int i = 0; i < 4; i++) lac[t][i] = 0.f;
    }

    attn_stage(sbase, 0, 0, b, h, tid);
    CP_COMMIT();

    for (int ck = 0; ck < 8; ++ck) {
        const int buf = ck & 1;

        if (ck < 7) {
            attn_stage(sbase, (ck + 1) & 1, (ck + 1) << 7, b, h, tid);
            CP_COMMIT();
            asm volatile("cp.async.wait_group 1;" ::: "memory");
        } else {
            asm volatile("cp.async.wait_group 0;" ::: "memory");
        }
        __syncthreads();

        const uint32_t aKh = sbase + (uint32_t)buf * BUFB + kOff;
        const uint32_t aKl = aKh + CHUNKB;
        const uint32_t aVh = sbase + (uint32_t)buf * BUFB + 2 * CHUNKB + vOff;

        uint32_t mwa[2][4], mwb[2][4];
        #pragma unroll
        for (int t = 0; t < 2; t++) {
            uint4 a = mbase[mrowA[t] + ck];
            uint4 bq = mbase[mrowB[t] + ck];
            mwa[t][0] = a.x;  mwa[t][1] = a.y;  mwa[t][2] = a.z;  mwa[t][3] = a.w;
            mwb[t][0] = bq.x; mwb[t][1] = bq.y; mwb[t][2] = bq.z; mwb[t][3] = bq.w;
        }

        #pragma unroll
        for (int s = 0; s < 8; ++s) {
            const uint32_t so = (uint32_t)(s * 16 * KROWB);
            uint32_t kh[4], kl[4], vh[4];
            ldm_x4(kh, aKh + so);
            ldm_x4(kl, aKl + so);
            ldm_x4_t(vh, aVh + so);
            const int sh = ((s & 1) << 4) + d0;

            #pragma unroll
            for (int t = 0; t < 2; t++) {
                float cA0[4] = {0.f, 0.f, 0.f, 0.f};
                float cB0[4] = {0.f, 0.f, 0.f, 0.f};
                float cA1[4] = {0.f, 0.f, 0.f, 0.f};
                float cB1[4] = {0.f, 0.f, 0.f, 0.f};
                mma_bf16(cA0, ah[t], kh[0], kh[1]);
                mma_bf16(cB0, ah[t], kl[0], kl[1]);
                mma_bf16(cA1, ah[t], kh[2], kh[3]);
                mma_bf16(cB1, ah[t], kl[2], kl[3]);
                mma_bf16(cB0, al[t], kh[0], kh[1]);
                mma_bf16(cB1, al[t], kh[2], kh[3]);

                uint32_t wa = mwa[t][s >> 1] >> sh;
                uint32_t wb = mwb[t][s >> 1] >> sh;

                float p00 = (wa & 1u)     ? 0.f : ex2f(cA0[0] + cB0[0]);
                float p01 = (wa & 2u)     ? 0.f : ex2f(cA0[1] + cB0[1]);
                float p02 = (wb & 1u)     ? 0.f : ex2f(cA0[2] + cB0[2]);
                float p03 = (wb & 2u)     ? 0.f : ex2f(cA0[3] + cB0[3]);
                float p10 = (wa & 0x100u) ? 0.f : ex2f(cA1[0] + cB1[0]);
                float p11 = (wa & 0x200u) ? 0.f : ex2f(cA1[1] + cB1[1]);
                float p12 = (wb & 0x100u) ? 0.f : ex2f(cA1[2] + cB1[2]);
                float p13 = (wb & 0x200u) ? 0.f : ex2f(cA1[3] + cB1[3]);

                uint32_t ap[4];
                ap[0] = pack_bf16x2(p00, p01);
                ap[1] = pack_bf16x2(p02, p03);
                ap[2] = pack_bf16x2(p10, p11);
                ap[3] = pack_bf16x2(p12, p13);

                mma_bf16(o[t][0], ap, vh[0], vh[1]);
                mma_bf16(o[t][1], ap, vh[2], vh[3]);
                mma_bf16(lac[t], ap, ONES2, ONES2);
            }
        }
        __syncthreads();
    }

    #pragma unroll
    for (int t = 0; t < 2; t++) {
        float ia = (lac[t][0] > 0.f) ? __fdividef(1.f, lac[t][0]) : 0.f;
        float ib = (lac[t][2] > 0.f) ? __fdividef(1.f, lac[t][2]) : 0.f;
        int rowA = q0 + w * 32 + t * 16 + rq;
        float* oA = ctx + (size_t)(b * L_ + rowA) * D_ + h * HD_;
        float* oB = oA + (size_t)8 * D_;
        #pragma unroll
        for (int n = 0; n < 2; n++) {
            *(float2*)(oA + n * 8 + d0) = make_float2(o[t][n][0] * ia, o[t][n][1] * ia);
            *(float2*)(oB + n * 8 + d0) = make_float2(o[t][n][2] * ib, o[t][n][3] * ib);
        }
    }
}

// -------- residual add + LayerNorm -> hi/lo planes (2 rows per block) ------
__global__ __launch_bounds__(256) void add_ln_kernel(
    const float* __restrict__ xin, const float* __restrict__ r,
    const float* __restrict__ gamma, const float* __restrict__ beta,
    __nv_bfloat16* __restrict__ oh, __nv_bfloat16* __restrict__ ol)
{
    const int half = threadIdx.x >> 7;
    const int t    = threadIdx.x & 127;
    const int row  = blockIdx.x * 2 + half;
    const int warp = threadIdx.x >> 5, lane = threadIdx.x & 31;
    __shared__ float red1[8], red2[8];

    float v = xin[(size_t)row * D_ + t] + r[(size_t)row * D_ + t];

    float s = v;
    #pragma unroll
    for (int o = 16; o; o >>= 1) s += __shfl_xor_sync(0xffffffffu, s, o);
    if (lane == 0) red1[warp] = s;
    __syncthreads();
    const int wb = half * 4;
    float mu = (red1[wb] + red1[wb+1] + red1[wb+2] + red1[wb+3]) * (1.f / D_);

    float c = v - mu;
    float q = c * c;
    #pragma unroll
    for (int o = 16; o; o >>= 1) q += __shfl_xor_sync(0xffffffffu, q, o);
    if (lane == 0) red2[warp] = q;
    __syncthreads();
    float var = (red2[wb] + red2[wb+1] + red2[wb+2] + red2[wb+3]) * (1.f / D_);

    float y = c * rsqrtf(var + LN_EPS) * gamma[t] + beta[t];
    float hy = bfr(y);
    oh[(size_t)row * D_ + t] = __float2bfloat16_rn(hy);
    ol[(size_t)row * D_ + t] = __float2bfloat16_rn(y - hy);
}

// ====== fused FFN BM=128, 512 thr, single wave (grid=128) ===================
#define FFN_SA  0u
#define FFN_SW1 65536u
#define FFN_SW2 131072u
#define FFN_SMEM (192 * 1024)
__global__ __launch_bounds__(512) void hmma_ffn_ln(
    const float* __restrict__ b1, const float* __restrict__ b2,
    const float* __restrict__ gamma, const float* __restrict__ beta,
    float* __restrict__ out)
{
    extern __shared__ __align__(16) uint8_t dsm[];
    const uint32_t sbase = smem_u32(dsm);

    const int tid  = threadIdx.x;
    const int lane = tid & 31;
    const int w    = tid >> 5;
    const int wm   = w & 7;
    const int wn   = w >> 3;
    const int m0   = blockIdx.x * 128;

    const int rq = lane >> 2;
    const int d0 = (lane & 3) * 2;
    const int lr16  = lane & 15;
    const int lclog = lane >> 4;
    const int lm = lane >> 3, lr = lane & 7;

    #pragma unroll
    for (int rep = 0; rep < 8; ++rep) {
        int idx = rep * 512 + tid;
        int plane = idx >> 11, kh = (idx >> 10) & 1, row = (idx >> 3) & 127, chunk = idx & 7;
        const __nv_bfloat16* src = (plane ? g_x1l : g_x1h)
            + (size_t)(m0 + row) * 128 + kh * 64 + chunk * 8;
        uint32_t dst = sbase + FFN_SA + (uint32_t)(plane * 32768 + kh * 16384 + row * 128
                     + (((chunk ^ (row & 7))) << 4));
        cp16(dst, src);
    }
    #pragma unroll
    for (int rep = 0; rep < 8; ++rep) {
        int idx = rep * 512 + tid;
        int plane = idx >> 11, nh = (idx >> 10) & 1, kr = (idx >> 3) & 127, chunk = idx & 7;
        const __nv_bfloat16* src = (plane ? g_w1l : g_w1h)
            + (size_t)kr * 128 + nh * 64 + chunk * 8;
        uint32_t dst = sbase + FFN_SW1 + (uint32_t)(plane * 32768 + nh * 16384 + kr * 128
                     + (((chunk ^ (kr & 7))) << 4));
        cp16(dst, src);
    }
    CP_COMMIT();
    #pragma unroll
    for (int rep = 0; rep < 8; ++rep) {
        int idx = rep * 512 + tid;
        int plane = idx >> 11, nh = (idx >> 10) & 1, kr = (idx >> 3) & 127, chunk = idx & 7;
        const __nv_bfloat16* src = (plane ? g_w2l : g_w2h)
            + (size_t)kr * 128 + nh * 64 + chunk * 8;
        uint32_t dst = sbase + FFN_SW2 + (uint32_t)(plane * 32768 + nh * 16384 + kr * 128
                     + (((chunk ^ (kr & 7))) << 4));
        cp16(dst, src);
    }
    CP_COMMIT();

    float c[8][4];
    #pragma unroll
    for (int i = 0; i < 8; i++)
        #pragma unroll
        for (int j = 0; j < 4; j++) c[i][j] = 0.f;

    asm volatile("cp.async.wait_group 1;" ::: "memory");
    __syncthreads();

    const int rowA = wm * 16 + lr16;
    // GEMM1: T = relu(x1 @ w1 + b1)
    #pragma unroll
    for (int s = 0; s < 8; ++s) {
        const int kh = s >> 2, sl = s & 3;
        uint32_t ah[4], al[4];
        {
            uint32_t off = FFN_SA + (uint32_t)(kh * 16384 + rowA * 128
                         + ((((sl * 2 + lclog) ^ (rowA & 7))) << 4));
            ldm_x4(ah, sbase + off);
            ldm_x4(al, sbase + off + 32768);
        }
        int rowB = s * 16 + ((lm & 1) << 3) + lr;
        uint32_t rbase = FFN_SW1 + (uint32_t)(wn * 16384 + rowB * 128);
        #pragma unroll
        for (int g = 0; g < 4; ++g) {
            uint32_t chunk = (uint32_t)(g * 2 + (lm >> 1));
            uint32_t off = rbase + ((chunk ^ (rowB & 7)) << 4);
            uint32_t bh[4], bl[4];
            ldm_x4_t(bh, sbase + off);
            ldm_x4_t(bl, sbase + off + 32768);
            mma_bf16(c[g*2],   ah, bh[0], bh[1]);
            mma_bf16(c[g*2],   ah, bl[0], bl[1]);
            mma_bf16(c[g*2],   al, bh[0], bh[1]);
            mma_bf16(c[g*2+1], ah, bh[2], bh[3]);
            mma_bf16(c[g*2+1], ah, bl[2], bl[3]);
            mma_bf16(c[g*2+1], al, bh[2], bh[3]);
        }
    }

    __syncthreads();
    {
        const int rowT = wm * 16 + rq;
        #pragma unroll
        for (int t8 = 0; t8 < 8; ++t8) {
            int col = wn * 64 + t8 * 8 + d0;
            float bb0 = b1[col], bb1 = b1[col + 1];
            float v00 = fmaxf(c[t8][0] + bb0, 0.f), v01 = fmaxf(c[t8][1] + bb1, 0.f);
            float v10 = fmaxf(c[t8][2] + bb0, 0.f), v11 = fmaxf(c[t8][3] + bb1, 0.f);
            float h00 = bfr(v00), h01 = bfr(v01), h10 = bfr(v10), h11 = bfr(v11);
            uint32_t off0 = FFN_SA + (uint32_t)(wn * 16384 + rowT * 128
                          + (((t8 ^ (rowT & 7))) << 4) + d0 * 2);
            uint32_t off1 = FFN_SA + (uint32_t)(wn * 16384 + (rowT + 8) * 128
                          + (((t8 ^ ((rowT + 8) & 7))) << 4) + d0 * 2);
            *(uint32_t*)(dsm + off0)           = pack_bf16x2(h00, h01);
            *(uint32_t*)(dsm + off0 + 32768)   = pack_bf16x2(v00 - h00, v01 - h01);
            *(uint32_t*)(dsm + off1)           = pack_bf16x2(h10, h11);
            *(uint32_t*)(dsm + off1 + 32768)   = pack_bf16x2(v10 - h10, v11 - h11);
        }
    }
    asm volatile("cp.async.wait_group 0;" ::: "memory");
    __syncthreads();

    // GEMM2: Y = T @ w2
    #pragma unroll
    for (int i = 0; i < 8; i++)
        #pragma unroll
        for (int j = 0; j < 4; j++) c[i][j] = 0.f;

    #pragma unroll
    for (int s = 0; s < 8; ++s) {
        const int kh = s >> 2, sl = s & 3;
        uint32_t ah[4], al[4];
        {
            uint32_t off = FFN_SA + (uint32_t)(kh * 16384 + rowA * 128
                         + ((((sl * 2 + lclog) ^ (rowA & 7))) << 4));
            ldm_x4(ah, sbase + off);
            ldm_x4(al, sbase + off + 32768);
        }
        int rowB = s * 16 + ((lm & 1) << 3) + lr;
        uint32_t rbase = FFN_SW2 + (uint32_t)(wn * 16384 + rowB * 128);
        #pragma unroll
        for (int g = 0; g < 4; ++g) {
            uint32_t chunk = (uint32_t)(g * 2 + (lm >> 1));
            uint32_t off = rbase + ((chunk ^ (rowB & 7)) << 4);
            uint32_t bh[4], bl[4];
            ldm_x4_t(bh, sbase + off);
            ldm_x4_t(bl, sbase + off + 32768);
            mma_bf16(c[g*2],   ah, bh[0], bh[1]);
            mma_bf16(c[g*2],   ah, bl[0], bl[1]);
            mma_bf16(c[g*2],   al, bh[0], bh[1]);
            mma_bf16(c[g*2+1], ah, bh[2], bh[3]);
            mma_bf16(c[g*2+1], ah, bl[2], bl[3]);
            mma_bf16(c[g*2+1], al, bh[2], bh[3]);
        }
    }

    __syncthreads();
    float* sC = (float*)(dsm + FFN_SW1);
    {
        const int rowT = wm * 16 + rq;
        #pragma unroll
        for (int t8 = 0; t8 < 8; ++t8) {
            int col = wn * 64 + t8 * 8 + d0;
            float bb0 = b2[col], bb1 = b2[col + 1];
            sC[rowT * 128 + col]           = c[t8][0] + bb0;
            sC[rowT * 128 + col + 1]       = c[t8][1] + bb1;
            sC[(rowT + 8) * 128 + col]     = c[t8][2] + bb0;
            sC[(rowT + 8) * 128 + col + 1] = c[t8][3] + bb1;
        }
    }
    __syncthreads();

    {
        const int row = tid >> 2;
        const int q4 = tid & 3;
        float* vr = sC + row * 128 + q4 * 32;
        const __nv_bfloat16* xh = g_x1h + (size_t)(m0 + row) * 128 + q4 * 32;
        const __nv_bfloat16* xl = g_x1l + (size_t)(m0 + row) * 128 + q4 * 32;

        float s = 0.f;
        #pragma unroll
        for (int j = 0; j < 32; j++) {
            float x = __bfloat162float(xh[j]) + __bfloat162float(xl[j]);
            float v = vr[j] + x;
            vr[j] = v;
            s += v;
        }
        s += __shfl_xor_sync(0xffffffffu, s, 1);
        s += __shfl_xor_sync(0xffffffffu, s, 2);
        float mu = s * (1.f / 128.f);

        float q = 0.f;
        #pragma unroll
        for (int j = 0; j < 32; j++) {
            float d = vr[j] - mu;
            q += d * d;
        }
        q += __shfl_xor_sync(0xffffffffu, q, 1);
        q += __shfl_xor_sync(0xffffffffu, q, 2);
        float rs = rsqrtf(q * (1.f / 128.f) + LN_EPS);

        float* orow = out + (size_t)(m0 + row) * 128 + q4 * 32;
        #pragma unroll
        for (int j = 0; j < 32; j++) {
            orow[j] = (vr[j] - mu) * rs * gamma[q4 * 32 + j] + beta[q4 * 32 + j];
        }
    }
}

// ---------------- launch --------------------------------------------------
extern "C" void kernel_launch(void* const* d_in, const int* in_sizes, int n_in,
                              void* d_out, int out_size)
{
    const float* edge_x    = (const float*)d_in[0];
    const void*  edge_mask = d_in[1];
    const float* in_proj_w = (const float*)d_in[2];
    const float* in_proj_b = (const float*)d_in[3];
    const float* w1        = (const float*)d_in[4];
    const float* b1        = (const float*)d_in[5];
    const float* w2        = (const float*)d_in[6];
    const float* b2        = (const float*)d_in[7];
    const float* g1        = (const float*)d_in[8];
    const float* beta1     = (const float*)d_in[9];
    const float* g2        = (const float*)d_in[10];
    const float* beta2     = (const float*)d_in[11];
    float* out = (float*)d_out;

    cudaFuncSetAttribute(qkv_gemm_kernel, cudaFuncAttributeMaxDynamicSharedMemorySize, QKV_SMEM);
    cudaFuncSetAttribute(hmma_ffn_ln,     cudaFuncAttributeMaxDynamicSharedMemorySize, FFN_SMEM);

    void *p_ctx, *p_x1h, *p_x1l;
    cudaGetSymbolAddress(&p_ctx, g_ctx);
    cudaGetSymbolAddress(&p_x1h, g_x1h);
    cudaGetSymbolAddress(&p_x1l, g_x1l);

    // 0) mask dtype detect (parallel)
    detect_mask_kernel<<<1, 256>>>((const unsigned char*)edge_mask);

    // 1) unified prep
    prep_kernel<<<(PREP_N + 255) / 256, 256>>>(edge_mask, edge_x, in_proj_w, w1, w2);

    // 2) QKV projection (khalf-pipelined)
    {
        dim3 grid(3, ROWS / 64);
        qkv_gemm_kernel<<<grid, 256, QKV_SMEM>>>(in_proj_b);
    }

    // 3) masked attention -> normalized ctx (R14 double-buffer config)
    {
        dim3 grid(L_ / 128, B_ * H_);
        attn_mma_kernel<<<grid, 128>>>((float*)p_ctx);
    }

    // 4) x1 = LN(edge_x + ctx) -> hi/lo planes
    add_ln_kernel<<<ROWS / 2, 256>>>(edge_x, (const float*)p_ctx,
                                     g1, beta1,
                                     (__nv_bfloat16*)p_x1h, (__nv_bfloat16*)p_x1l);

    // 5) fused FFN (single wave)
    hmma_ffn_ln<<<ROWS / 128, 512, FFN_SMEM>>>(b1, b2, g2, beta2, out);
}